// round 15
// baseline (speedup 1.0000x reference)
#include <cuda_runtime.h>
#include <cuda_fp16.h>
#include <stdint.h>

#define EMB   384
#define HEADS 6
#define DFF   1536
#define BB    32
#define TT    512
#define ROWS  (BB*TT)

// Chunked-SW128 layout: 16KB blocks of [128 rows][64 halves];
// block = (row>>7)*(K/64) + (k>>6); byte = sw128((row&127)*128 + (k&63)*2)
__device__ __half g_h [ROWS*EMB];
__device__ __half g_q [ROWS*EMB];     // [B,H,T,D] linear, pre-scaled 0.125*log2e
__device__ __half g_k [ROWS*EMB];     // [B,H,T,D] linear
__device__ __half g_v [ROWS*EMB];     // [B,H,D,T] linear (transposed)
__device__ __half g_o [ROWS*EMB];     // attn out, chunked K=384
__device__ __half g_h2[ROWS*EMB];
__device__ __half g_ff[ROWS*DFF];
__device__ __half g_wqkv[3*EMB*EMB];
__device__ __half g_wp [EMB*EMB];
__device__ __half g_w1t[DFF*EMB];
__device__ __half g_w2t[EMB*DFF];

__device__ __forceinline__ uint32_t h2u(__half2 h) { return *(uint32_t*)&h; }
__device__ __forceinline__ void cp16(uint32_t saddr, const void* gptr) {
    asm volatile("cp.async.cg.shared.global [%0], [%1], 16;" :: "r"(saddr), "l"(gptr));
}
__device__ __forceinline__ uint32_t sw128(uint32_t off) {
    return off ^ ((off >> 3) & 0x70);
}
__device__ __forceinline__ void mwait(uint32_t mbar, uint32_t parity) {
    asm volatile(
        "{\n\t.reg .pred P;\n\tMW%=:\n\t"
        "mbarrier.try_wait.parity.acquire.cta.shared::cta.b64 P, [%0], %1;\n\t"
        "@!P bra MW%=;\n\t}" :: "r"(mbar), "r"(parity) : "memory");
}
__device__ __forceinline__ void bulk_ld(uint32_t saddr, const void* g, uint32_t bytes,
                                        uint32_t mbar) {
    asm volatile("cp.async.bulk.shared::cluster.global.mbarrier::complete_tx::bytes "
                 "[%0], [%1], %2, [%3];"
                 :: "r"(saddr), "l"(g), "r"(bytes), "r"(mbar) : "memory");
}
__device__ __forceinline__ void ldsm4(uint32_t& r0, uint32_t& r1, uint32_t& r2,
                                      uint32_t& r3, uint32_t a) {
    asm volatile("ldmatrix.sync.aligned.m8n8.x4.shared.b16 {%0,%1,%2,%3}, [%4];"
                 : "=r"(r0), "=r"(r1), "=r"(r2), "=r"(r3) : "r"(a));
}

// ---- fused weight transpose + fp16 + chunked swizzle ----
__global__ void trans_all(const float* Wq, const float* Wk, const float* Wv,
                          const float* Wp, const float* W1, const float* W2,
                          __half* wqkv, __half* wp, __half* w1t, __half* w2t) {
    __shared__ float t[32][33];
    int id = blockIdx.x;
    const float* src; __half* dst; int K, N;
    if (id < 576) {
        int w = id / 144; id -= w * 144;
        src = (w == 0) ? Wq : (w == 1) ? Wk : (w == 2) ? Wv : Wp;
        dst = (w < 3) ? (wqkv + (size_t)w * EMB * EMB) : wp;
        K = 384; N = 384;
    } else if (id < 1152) { id -= 576;  src = W1; dst = w1t; K = 384;  N = 1536; }
    else                  { id -= 1152; src = W2; dst = w2t; K = 1536; N = 384;  }
    int ntn = N / 32;
    int n0 = (id % ntn) * 32, k0 = (id / ntn) * 32;
    int tx = threadIdx.x, ty = threadIdx.y;
    #pragma unroll
    for (int j = 0; j < 4; j++)
        t[ty + 8*j][tx] = src[(size_t)(k0 + ty + 8*j) * N + n0 + tx];
    __syncthreads();
    int KB = K >> 6;
    #pragma unroll
    for (int j = 0; j < 4; j++) {
        int n = n0 + ty + 8*j, k = k0 + tx;
        int blk = (n >> 7) * KB + (k >> 6);
        uint32_t bo = sw128((uint32_t)(n & 127) * 128 + (uint32_t)(k & 63) * 2);
        *(__half*)((char*)dst + (size_t)blk * 16384 + bo) = __float2half_rn(t[tx][ty + 8*j]);
    }
}

// ---- LayerNorm: warp-per-row, single-pass, float4 -> chunked fp16 (K=384) ----
__global__ void __launch_bounds__(256)
ln_kernel(const float* __restrict__ x, const float* __restrict__ g,
          const float* __restrict__ b, __half* __restrict__ out) {
    int warp = threadIdx.x >> 5, lane = threadIdx.x & 31;
    int row = blockIdx.x * 8 + warp;
    const float4* xr = (const float4*)(x + (size_t)row * EMB);
    float4 v[3];
    float s1 = 0.f, s2 = 0.f;
    #pragma unroll
    for (int j = 0; j < 3; j++) {
        v[j] = xr[lane + 32 * j];
        s1 += v[j].x + v[j].y + v[j].z + v[j].w;
        s2 += v[j].x*v[j].x + v[j].y*v[j].y + v[j].z*v[j].z + v[j].w*v[j].w;
    }
    #pragma unroll
    for (int o = 16; o; o >>= 1) {
        s1 += __shfl_xor_sync(0xffffffffu, s1, o);
        s2 += __shfl_xor_sync(0xffffffffu, s2, o);
    }
    float mu = s1 * (1.0f / EMB);
    float var = s2 * (1.0f / EMB) - mu * mu;
    float inv = rsqrtf(var + 1e-5f);

    char* ob = (char*)out;
    uint32_t rb = (uint32_t)(row & 127) * 128;
    int mb6 = (row >> 7) * 6;
    #pragma unroll
    for (int j = 0; j < 3; j++) {
        int k = (lane + 32 * j) * 4;
        float4 gv = *(const float4*)&g[k];
        float4 bv = *(const float4*)&b[k];
        float o0 = (v[j].x - mu) * inv * gv.x + bv.x;
        float o1 = (v[j].y - mu) * inv * gv.y + bv.y;
        float o2 = (v[j].z - mu) * inv * gv.z + bv.z;
        float o3 = (v[j].w - mu) * inv * gv.w + bv.w;
        uint2 u;
        u.x = h2u(__floats2half2_rn(o0, o1));
        u.y = h2u(__floats2half2_rn(o2, o3));
        *(uint2*)(ob + (size_t)(mb6 + (k >> 6)) * 16384 + sw128(rb + (uint32_t)(k & 63) * 2)) = u;
    }
}

// ---- FP16 warp-MMA GEMM: bulk-copy loads (hoisted) + ldmatrix fragments ----
#define HG_HDR 1024
#define HG_BUF 16384
#define HG_STAGE (2 * HG_BUF)
#define HG_SMEM (HG_HDR + 3 * HG_STAGE)

template<int EPI>
__global__ void __launch_bounds__(256)
hgemm(const __half* __restrict__ A, const __half* __restrict__ W,
      const float* __restrict__ bias, const float* __restrict__ R,
      void* __restrict__ Cv, __half* qO, __half* kO, __half* vO, int N, int K) {
    extern __shared__ char smem[];
    uint32_t sb = (uint32_t)__cvta_generic_to_shared(smem);
    int tid  = threadIdx.x;
    int lane = tid & 31, warp = tid >> 5;
    int wm = warp >> 2, wn = warp & 3;
    int l4 = lane >> 2, qq = lane & 3;
    int n0 = blockIdx.x * 128, m0 = blockIdx.y * 128;
    int KB = K >> 6;
    int mbA = blockIdx.y, nbB = blockIdx.x;
    const char* Ab = (const char*)A;
    const char* Wb = (const char*)W;

    uint32_t aRow = (uint32_t)((lane & 7) + ((lane >> 3) & 1) * 8);
    uint32_t aSel = (uint32_t)((lane >> 4) * 16);
    uint32_t bRow = (uint32_t)(((lane >> 4) & 1) * 8 + (lane & 7));
    uint32_t bSel = (uint32_t)(((lane >> 3) & 1) * 16);
    uint32_t xm   = (uint32_t)((lane & 7) << 4);
    uint32_t aBase = (uint32_t)(wm * 64) + aRow;
    uint32_t bBase = (uint32_t)(wn * 32) + bRow;

    if (tid < 3)
        asm volatile("mbarrier.init.shared.b64 [%0], 1;" :: "r"(sb + tid * 8) : "memory");
    __syncthreads();

    auto load = [&](int c) {
        int st = c % 3;
        uint32_t mb = sb + st * 8;
        uint32_t d  = sb + HG_HDR + (uint32_t)st * HG_STAGE;
        asm volatile("mbarrier.arrive.expect_tx.shared.b64 _, [%0], %1;"
                     :: "r"(mb), "r"((uint32_t)HG_STAGE) : "memory");
        bulk_ld(d,          Ab + (size_t)(mbA * KB + c) * HG_BUF, HG_BUF, mb);
        bulk_ld(d + HG_BUF, Wb + (size_t)(nbB * KB + c) * HG_BUF, HG_BUF, mb);
    };
    if (tid == 0) { load(0); load(1); }

    float acc[4][4][4];
    #pragma unroll
    for (int mt = 0; mt < 4; mt++)
        #pragma unroll
        for (int nt = 0; nt < 4; nt++)
            #pragma unroll
            for (int e = 0; e < 4; e++) acc[mt][nt][e] = 0.f;

    for (int c = 0; c < KB; c++) {
        int st = c % 3;
        mwait(sb + st * 8, (uint32_t)((c / 3) & 1));
        // buffer (c-1)%3 is free (sync of iter c-1 passed) -> issue its refill NOW
        if (c + 2 < KB && tid == 0) load(c + 2);
        uint32_t As = sb + HG_HDR + (uint32_t)st * HG_STAGE;
        uint32_t Bs = As + HG_BUF;

        #pragma unroll
        for (int kk = 0; kk < 4; kk++) {
            uint32_t af[4][4], bf[4][2];
            #pragma unroll
            for (int mt = 0; mt < 4; mt++)
                ldsm4(af[mt][0], af[mt][1], af[mt][2], af[mt][3],
                      As + (aBase + mt * 16) * 128 + ((32u * kk + aSel) ^ xm));
            #pragma unroll
            for (int pr = 0; pr < 2; pr++)
                ldsm4(bf[2*pr][0], bf[2*pr][1], bf[2*pr+1][0], bf[2*pr+1][1],
                      Bs + (bBase + pr * 16) * 128 + ((32u * kk + bSel) ^ xm));
            #pragma unroll
            for (int mt = 0; mt < 4; mt++)
                #pragma unroll
                for (int nt = 0; nt < 4; nt++)
                    asm volatile(
                        "mma.sync.aligned.m16n8k16.row.col.f32.f16.f16.f32 "
                        "{%0,%1,%2,%3}, {%4,%5,%6,%7}, {%8,%9}, {%0,%1,%2,%3};"
                        : "+f"(acc[mt][nt][0]), "+f"(acc[mt][nt][1]),
                          "+f"(acc[mt][nt][2]), "+f"(acc[mt][nt][3])
                        : "r"(af[mt][0]), "r"(af[mt][1]), "r"(af[mt][2]), "r"(af[mt][3]),
                          "r"(bf[nt][0]), "r"(bf[nt][1]));
        }
        __syncthreads();
    }

    #pragma unroll
    for (int mt = 0; mt < 4; mt++) {
        #pragma unroll
        for (int nt = 0; nt < 4; nt++) {
            int nb = n0 + wn * 32 + nt * 8 + qq * 2;
            int mA = m0 + wm * 64 + mt * 16 + l4;
            float v0 = acc[mt][nt][0], v1 = acc[mt][nt][1];
            float v2 = acc[mt][nt][2], v3 = acc[mt][nt][3];
            if (EPI == 0) {
                int mat = nb / 384, nn = nb - mat * 384;
                int head = nn >> 6, d = nn & 63;
                int b_ = mA >> 9, tA = mA & 511;
                if (mat == 0) {
                    const float qs = 0.125f * 1.4426950408889634f;   // fold log2e
                    v0 *= qs; v1 *= qs; v2 *= qs; v3 *= qs;
                }
                if (mat < 2) {
                    __half* base = mat ? kO : qO;
                    size_t off0 = ((size_t)(b_ * HEADS + head) * TT + tA) * 64 + d;
                    *(__half2*)&base[off0]          = __floats2half2_rn(v0, v1);
                    *(__half2*)&base[off0 + 8 * 64] = __floats2half2_rn(v2, v3);
                } else {
                    size_t off0 = ((size_t)(b_ * HEADS + head) * 64 + d) * TT + tA;
                    vO[off0]          = __float2half_rn(v0);
                    vO[off0 + TT]     = __float2half_rn(v1);
                    vO[off0 + 8]      = __float2half_rn(v2);
                    vO[off0 + TT + 8] = __float2half_rn(v3);
                }
            } else if (EPI == 1) {
                float* Cf = (float*)Cv;
                size_t o0 = (size_t)mA * N + nb;
                size_t o1 = (size_t)(mA + 8) * N + nb;
                Cf[o0]     = v0 + bias[nb]     + R[o0];
                Cf[o0 + 1] = v1 + bias[nb + 1] + R[o0 + 1];
                Cf[o1]     = v2 + bias[nb]     + R[o1];
                Cf[o1 + 1] = v3 + bias[nb + 1] + R[o1 + 1];
            } else {
                char* Ch = (char*)Cv;
                v0 += bias[nb];     v1 += bias[nb + 1];
                v2 += bias[nb];     v3 += bias[nb + 1];
                v0 = v0 > 0.f ? v0 : 0.f;  v1 = v1 > 0.f ? v1 : 0.f;
                v2 = v2 > 0.f ? v2 : 0.f;  v3 = v3 > 0.f ? v3 : 0.f;
                int blk = (mA >> 7) * (N >> 6) + (nb >> 6);
                uint32_t b0 = sw128((uint32_t)(mA & 127) * 128 + (uint32_t)(nb & 63) * 2);
                uint32_t b1 = sw128((uint32_t)((mA + 8) & 127) * 128 + (uint32_t)(nb & 63) * 2);
                *(__half2*)(Ch + (size_t)blk * 16384 + b0) = __floats2half2_rn(v0, v1);
                *(__half2*)(Ch + (size_t)blk * 16384 + b1) = __floats2half2_rn(v2, v3);
            }
        }
    }
}

// ---- fp16 flash attention: ldmatrix K/V, base-2 softmax, 128-key pairs ----
// 4 K buffers + 4 V buffers, each 64 keys x 128B swizzled rows.
#define KVB 8192
#define ATTN_SMEM (8 * KVB)   // 65536

__global__ void __launch_bounds__(256)
attn3_kernel(const __half* __restrict__ q, const __half* __restrict__ k,
             const __half* __restrict__ v, __half* __restrict__ o) {
    extern __shared__ char sm2[];
    uint32_t sbase = (uint32_t)__cvta_generic_to_shared(sm2);
    int tid = threadIdx.x, lane = tid & 31, warp = tid >> 5;
    int l4 = lane >> 2, qq = lane & 3;
    int bh = blockIdx.y;
    int q0 = (int)(gridDim.x - 1 - blockIdx.x) * 128;   // heavy tiles first
    int mrow = warp * 16 + l4, qg0 = q0 + mrow, qg1 = qg0 + 8;
    int pairs = (q0 + 128) >> 7;    // ktiles/2, ktiles even
    int lr = tid >> 2, lc = tid & 3;
    uint32_t lxm = (uint32_t)((lr & 7) << 4);
    const __half* kh = k + (size_t)bh * TT * 64;
    const __half* vh = v + (size_t)bh * 64 * TT;

    uint32_t bRow = (uint32_t)(((lane >> 4) & 1) * 8 + (lane & 7));
    uint32_t bSel = (uint32_t)(((lane >> 3) & 1) * 16);
    uint32_t xm   = (uint32_t)((lane & 7) << 4);

    // prefetch pair 0 (tiles 0,1 -> slots 0,1)
    #pragma unroll
    for (int j = 0; j < 2; j++) {
        #pragma unroll
        for (int it = 0; it < 2; it++) {
            uint32_t c16 = (uint32_t)(lc + it * 4) * 16;
            uint32_t dof = (uint32_t)lr * 128 + (c16 ^ lxm);
            cp16(sbase + (uint32_t)j * KVB + dof,
                 kh + (size_t)(j * 64 + lr) * 64 + (c16 >> 1));
            cp16(sbase + (uint32_t)(4 + j) * KVB + dof,
                 vh + (size_t)lr * TT + j * 64 + (c16 >> 1));
        }
    }
    asm volatile("cp.async.commit_group;");

    const uint32_t* qw = (const uint32_t*)(q + (size_t)bh * TT * 64);
    uint32_t qf[4][4];
    #pragma unroll
    for (int kk = 0; kk < 4; kk++) {
        int kb = kk * 8;
        qf[kk][0] = qw[qg0 * 32 + kb + qq];
        qf[kk][1] = qw[qg1 * 32 + kb + qq];
        qf[kk][2] = qw[qg0 * 32 + kb + qq + 4];
        qf[kk][3] = qw[qg1 * 32 + kb + qq + 4];
    }

    float Oa[8][4];
    #pragma unroll
    for (int nt = 0; nt < 8; nt++)
        #pragma unroll
        for (int e = 0; e < 4; e++) Oa[nt][e] = 0.f;
    float m0 = -1e30f, m1 = -1e30f, l0 = 0.f, l1 = 0.f;

    for (int p2 = 0; p2 < pairs; p2++) {
        asm volatile("cp.async.wait_group 0;");
        __syncthreads();
        if (p2 + 1 < pairs) {
            int sbuf = 2 * ((p2 + 1) & 1);
            int tbase = 2 * (p2 + 1);
            #pragma unroll
            for (int j = 0; j < 2; j++) {
                #pragma unroll
                for (int it = 0; it < 2; it++) {
                    uint32_t c16 = (uint32_t)(lc + it * 4) * 16;
                    uint32_t dof = (uint32_t)lr * 128 + (c16 ^ lxm);
                    cp16(sbase + (uint32_t)(sbuf + j) * KVB + dof,
                         kh + (size_t)((tbase + j) * 64 + lr) * 64 + (c16 >> 1));
                    cp16(sbase + (uint32_t)(4 + sbuf + j) * KVB + dof,
                         vh + (size_t)lr * TT + (tbase + j) * 64 + (c16 >> 1));
                }
            }
            asm volatile("cp.async.commit_group;");
        }

        #pragma unroll
        for (int j = 0; j < 2; j++) {
            int slot = 2 * (p2 & 1) + j;
            uint32_t Ks = sbase + (uint32_t)slot * KVB;
            uint32_t Vs = sbase + (uint32_t)(4 + slot) * KVB;
            int k0 = (2 * p2 + j) << 6;

            float s[8][4];
            #pragma unroll
            for (int nt = 0; nt < 8; nt++)
                #pragma unroll
                for (int e = 0; e < 4; e++) s[nt][e] = 0.f;
            #pragma unroll
            for (int kk = 0; kk < 4; kk++) {
                uint32_t bf[8][2];
                #pragma unroll
                for (int pr = 0; pr < 4; pr++)
                    ldsm4(bf[2*pr][0], bf[2*pr][1], bf[2*pr+1][0], bf[2*pr+1][1],
                          Ks + (bRow + pr * 16) * 128 + ((32u * kk + bSel) ^ xm));
                #pragma unroll
                for (int nt = 0; nt < 8; nt++)
                    asm volatile(
                        "mma.sync.aligned.m16n8k16.row.col.f32.f16.f16.f32 "
                        "{%0,%1,%2,%3}, {%4,%5,%6,%7}, {%8,%9}, {%0,%1,%2,%3};"
                        : "+f"(s[nt][0]), "+f"(s[nt][1]), "+f"(s[nt][2]), "+f"(s[nt][3])
                        : "r"(qf[kk][0]), "r"(qf[kk][1]), "r"(qf[kk][2]), "r"(qf[kk][3]),
                          "r"(bf[nt][0]), "r"(bf[nt][1]));
            }
            if (k0 + 63 > qg0) {
                #pragma unroll
                for (int nt = 0; nt < 8; nt++) {
                    int kg = k0 + nt * 8 + 2 * qq;
                    if (kg     > qg0) s[nt][0] = -1e30f;
                    if (kg + 1 > qg0) s[nt][1] = -1e30f;
                    if (kg     > qg1) s[nt][2] = -1e30f;
                    if (kg + 1 > qg1) s[nt][3] = -1e30f;
                }
            }
            float r0 = -1e30f, r1 = -1e30f;
            #pragma unroll
            for (int nt = 0; nt < 8; nt++) {
                r0 = fmaxf(r0, fmaxf(s[nt][0], s[nt][1]));
                r1 = fmaxf(r1, fmaxf(s[nt][2], s[nt][3]));
            }
            r0 = fmaxf(r0, __shfl_xor_sync(0xffffffffu, r0, 1));
            r0 = fmaxf(r0, __shfl_xor_sync(0xffffffffu, r0, 2));
            r1 = fmaxf(r1, __shfl_xor_sync(0xffffffffu, r1, 1));
            r1 = fmaxf(r1, __shfl_xor_sync(0xffffffffu, r1, 2));
            float mn0 = fmaxf(m0, r0), mn1 = fmaxf(m1, r1);
            float sc0 = exp2f(m0 - mn0), sc1 = exp2f(m1 - mn1);
            float rs0 = 0.f, rs1 = 0.f;
            #pragma unroll
            for (int nt = 0; nt < 8; nt++) {
                s[nt][0] = exp2f(s[nt][0] - mn0);
                s[nt][1] = exp2f(s[nt][1] - mn0);
                s[nt][2] = exp2f(s[nt][2] - mn1);
                s[nt][3] = exp2f(s[nt][3] - mn1);
                rs0 += s[nt][0] + s[nt][1];
                rs1 += s[nt][2] + s[nt][3];
            }
            rs0 += __shfl_xor_sync(0xffffffffu, rs0, 1);
            rs0 += __shfl_xor_sync(0xffffffffu, rs0, 2);
            rs1 += __shfl_xor_sync(0xffffffffu, rs1, 1);
            rs1 += __shfl_xor_sync(0xffffffffu, rs1, 2);
            l0 = l0 * sc0 + rs0;  l1 = l1 * sc1 + rs1;
            m0 = mn0;  m1 = mn1;
            #pragma unroll
            for (int nt = 0; nt < 8; nt++) {
                Oa[nt][0] *= sc0; Oa[nt][1] *= sc0;
                Oa[nt][2] *= sc1; Oa[nt][3] *= sc1;
            }

            #pragma unroll
            for (int kk = 0; kk < 4; kk++) {
                uint32_t af[4];
                af[0] = h2u(__floats2half2_rn(s[2*kk][0],   s[2*kk][1]));
                af[1] = h2u(__floats2half2_rn(s[2*kk][2],   s[2*kk][3]));
                af[2] = h2u(__floats2half2_rn(s[2*kk+1][0], s[2*kk+1][1]));
                af[3] = h2u(__floats2half2_rn(s[2*kk+1][2], s[2*kk+1][3]));
                uint32_t bf[8][2];
                #pragma unroll
                for (int pr = 0; pr < 4; pr++)
                    ldsm4(bf[2*pr][0], bf[2*pr][1], bf[2*pr+1][0], bf[2*pr+1][1],
                          Vs + (bRow + pr * 16) * 128 + ((32u * kk + bSel) ^ xm));
                #pragma unroll
                for (int nt = 0; nt < 8; nt++)
                    asm volatile(
                        "mma.sync.aligned.m16n8k16.row.col.f32.f16.f16.f32 "
                        "{%0,%1,%2,%3}, {%4,%5,%6,%7}, {%8,%9}, {%0,%1,%2,%3};"
                        : "+f"(Oa[nt][0]), "+f"(Oa[nt][1]), "+f"(Oa[nt][2]), "+f"(Oa[nt][3])
                        : "r"(af[0]), "r"(af[1]), "r"(af[2]), "r"(af[3]),
                          "r"(bf[nt][0]), "r"(bf[nt][1]));
            }
        }
    }

    int b_ = bh / HEADS, h_ = bh % HEADS;
    float inv0 = 1.f / l0, inv1 = 1.f / l1;
    char* ob = (char*)o;
    int row0 = b_ * TT + qg0, row1 = b_ * TT + qg1;
    size_t blk0 = (size_t)((row0 >> 7) * 6 + h_) * 16384;
    size_t blk1 = (size_t)((row1 >> 7) * 6 + h_) * 16384;
    uint32_t rb0 = (uint32_t)(row0 & 127) * 128, rb1 = (uint32_t)(row1 & 127) * 128;
    #pragma unroll
    for (int nt = 0; nt < 8; nt++) {
        uint32_t co = (uint32_t)(nt * 8 + 2 * qq) * 2;
        *(__half2*)(ob + blk0 + sw128(rb0 + co)) = __floats2half2_rn(Oa[nt][0] * inv0, Oa[nt][1] * inv0);
        *(__half2*)(ob + blk1 + sw128(rb1 + co)) = __floats2half2_rn(Oa[nt][2] * inv1, Oa[nt][3] * inv1);
    }
}

// ---------------- launch ----------------
extern "C" void kernel_launch(void* const* d_in, const int* in_sizes, int n_in,
                              void* d_out, int out_size) {
    const float* x   = (const float*)d_in[0];
    const float* Wq  = (const float*)d_in[1];
    const float* Wk  = (const float*)d_in[2];
    const float* Wv  = (const float*)d_in[3];
    const float* Wp  = (const float*)d_in[4];
    const float* bp  = (const float*)d_in[5];
    const float* g1  = (const float*)d_in[6];
    const float* b1  = (const float*)d_in[7];
    const float* g2  = (const float*)d_in[8];
    const float* b2  = (const float*)d_in[9];
    const float* W1  = (const float*)d_in[10];
    const float* bf1 = (const float*)d_in[11];
    const float* W2  = (const float*)d_in[12];
    const float* bf2 = (const float*)d_in[13];
    float* out = (float*)d_out;

    __half *h, *q, *k, *v, *o, *h2, *ff, *wqkv, *wp, *w1t, *w2t;
    cudaGetSymbolAddress((void**)&h,    g_h);
    cudaGetSymbolAddress((void**)&q,    g_q);
    cudaGetSymbolAddress((void**)&k,    g_k);
    cudaGetSymbolAddress((void**)&v,    g_v);
    cudaGetSymbolAddress((void**)&o,    g_o);
    cudaGetSymbolAddress((void**)&h2,   g_h2);
    cudaGetSymbolAddress((void**)&ff,   g_ff);
    cudaGetSymbolAddress((void**)&wqkv, g_wqkv);
    cudaGetSymbolAddress((void**)&wp,   g_wp);
    cudaGetSymbolAddress((void**)&w1t,  g_w1t);
    cudaGetSymbolAddress((void**)&w2t,  g_w2t);

    static bool attr_done = false;
    if (!attr_done) {
        cudaFuncSetAttribute(attn3_kernel, cudaFuncAttributeMaxDynamicSharedMemorySize, (int)ATTN_SMEM);
        cudaFuncSetAttribute(hgemm<0>, cudaFuncAttributeMaxDynamicSharedMemorySize, (int)HG_SMEM);
        cudaFuncSetAttribute(hgemm<1>, cudaFuncAttributeMaxDynamicSharedMemorySize, (int)HG_SMEM);
        cudaFuncSetAttribute(hgemm<2>, cudaFuncAttributeMaxDynamicSharedMemorySize, (int)HG_SMEM);
        attr_done = true;
    }

    trans_all<<<1728, dim3(32, 8)>>>(Wq, Wk, Wv, Wp, W1, W2, wqkv, wp, w1t, w2t);
    ln_kernel<<<ROWS / 8, 256>>>(x, g1, b1, h);
    hgemm<0><<<dim3(9, ROWS/128), 256, HG_SMEM>>>(h, wqkv, nullptr, nullptr, nullptr, q, k, v, 1152, 384);
    attn3_kernel<<<dim3(TT/128, BB*HEADS), 256, ATTN_SMEM>>>(q, k, v, o);
    hgemm<1><<<dim3(3, ROWS/128), 256, HG_SMEM>>>(o, wp, bp, x, out, nullptr, nullptr, nullptr, 384, 384);
    ln_kernel<<<ROWS / 8, 256>>>(out, g2, b2, h2);
    hgemm<2><<<dim3(12, ROWS/128), 256, HG_SMEM>>>(h2, w1t, bf1, nullptr, ff, nullptr, nullptr, nullptr, 1536, 384);
    hgemm<1><<<dim3(3, ROWS/128), 256, HG_SMEM>>>(ff, w2t, bf2, out, out, nullptr, nullptr, nullptr, 384, 1536);
}

// round 16
// speedup vs baseline: 1.0333x; 1.0333x over previous
#include <cuda_runtime.h>
#include <cuda_fp16.h>
#include <stdint.h>

#define EMB   384
#define HEADS 6
#define DFF   1536
#define BB    32
#define TT    512
#define ROWS  (BB*TT)

// Chunked-SW128 layout: 16KB blocks of [128 rows][64 halves];
// block = (row>>7)*(K/64) + (k>>6); byte = sw128((row&127)*128 + (k&63)*2)
__device__ __half g_h [ROWS*EMB];
__device__ __half g_q [ROWS*EMB];     // [B,H,T,D] linear, pre-scaled 0.125*log2e
__device__ __half g_k [ROWS*EMB];     // [B,H,T,D] linear
__device__ __half g_v [ROWS*EMB];     // [B,H,D,T] linear (transposed)
__device__ __half g_o [ROWS*EMB];     // attn out, chunked K=384
__device__ __half g_h2[ROWS*EMB];
__device__ __half g_ff[ROWS*DFF];
__device__ __half g_wqkv[3*EMB*EMB];
__device__ __half g_wp [EMB*EMB];
__device__ __half g_w1t[DFF*EMB];
__device__ __half g_w2t[EMB*DFF];

__device__ __forceinline__ uint32_t h2u(__half2 h) { return *(uint32_t*)&h; }
__device__ __forceinline__ void cp16(uint32_t saddr, const void* gptr) {
    asm volatile("cp.async.cg.shared.global [%0], [%1], 16;" :: "r"(saddr), "l"(gptr));
}
__device__ __forceinline__ uint32_t sw128(uint32_t off) {
    return off ^ ((off >> 3) & 0x70);
}
__device__ __forceinline__ void mwait(uint32_t mbar, uint32_t parity) {
    asm volatile(
        "{\n\t.reg .pred P;\n\tMW%=:\n\t"
        "mbarrier.try_wait.parity.acquire.cta.shared::cta.b64 P, [%0], %1;\n\t"
        "@!P bra MW%=;\n\t}" :: "r"(mbar), "r"(parity) : "memory");
}
__device__ __forceinline__ void bulk_ld(uint32_t saddr, const void* g, uint32_t bytes,
                                        uint32_t mbar) {
    asm volatile("cp.async.bulk.shared::cluster.global.mbarrier::complete_tx::bytes "
                 "[%0], [%1], %2, [%3];"
                 :: "r"(saddr), "l"(g), "r"(bytes), "r"(mbar) : "memory");
}
__device__ __forceinline__ void ldsm4(uint32_t& r0, uint32_t& r1, uint32_t& r2,
                                      uint32_t& r3, uint32_t a) {
    asm volatile("ldmatrix.sync.aligned.m8n8.x4.shared.b16 {%0,%1,%2,%3}, [%4];"
                 : "=r"(r0), "=r"(r1), "=r"(r2), "=r"(r3) : "r"(a));
}

// ---- fused weight transpose + fp16 + chunked swizzle ----
__global__ void trans_all(const float* Wq, const float* Wk, const float* Wv,
                          const float* Wp, const float* W1, const float* W2,
                          __half* wqkv, __half* wp, __half* w1t, __half* w2t) {
    __shared__ float t[32][33];
    int id = blockIdx.x;
    const float* src; __half* dst; int K, N;
    if (id < 576) {
        int w = id / 144; id -= w * 144;
        src = (w == 0) ? Wq : (w == 1) ? Wk : (w == 2) ? Wv : Wp;
        dst = (w < 3) ? (wqkv + (size_t)w * EMB * EMB) : wp;
        K = 384; N = 384;
    } else if (id < 1152) { id -= 576;  src = W1; dst = w1t; K = 384;  N = 1536; }
    else                  { id -= 1152; src = W2; dst = w2t; K = 1536; N = 384;  }
    int ntn = N / 32;
    int n0 = (id % ntn) * 32, k0 = (id / ntn) * 32;
    int tx = threadIdx.x, ty = threadIdx.y;
    #pragma unroll
    for (int j = 0; j < 4; j++)
        t[ty + 8*j][tx] = src[(size_t)(k0 + ty + 8*j) * N + n0 + tx];
    __syncthreads();
    int KB = K >> 6;
    #pragma unroll
    for (int j = 0; j < 4; j++) {
        int n = n0 + ty + 8*j, k = k0 + tx;
        int blk = (n >> 7) * KB + (k >> 6);
        uint32_t bo = sw128((uint32_t)(n & 127) * 128 + (uint32_t)(k & 63) * 2);
        *(__half*)((char*)dst + (size_t)blk * 16384 + bo) = __float2half_rn(t[tx][ty + 8*j]);
    }
}

// ---- LayerNorm: warp-per-row, single-pass, float4 -> chunked fp16 (K=384) ----
__global__ void __launch_bounds__(256)
ln_kernel(const float* __restrict__ x, const float* __restrict__ g,
          const float* __restrict__ b, __half* __restrict__ out) {
    int warp = threadIdx.x >> 5, lane = threadIdx.x & 31;
    int row = blockIdx.x * 8 + warp;
    const float4* xr = (const float4*)(x + (size_t)row * EMB);
    float4 v[3];
    float s1 = 0.f, s2 = 0.f;
    #pragma unroll
    for (int j = 0; j < 3; j++) {
        v[j] = xr[lane + 32 * j];
        s1 += v[j].x + v[j].y + v[j].z + v[j].w;
        s2 += v[j].x*v[j].x + v[j].y*v[j].y + v[j].z*v[j].z + v[j].w*v[j].w;
    }
    #pragma unroll
    for (int o = 16; o; o >>= 1) {
        s1 += __shfl_xor_sync(0xffffffffu, s1, o);
        s2 += __shfl_xor_sync(0xffffffffu, s2, o);
    }
    float mu = s1 * (1.0f / EMB);
    float var = s2 * (1.0f / EMB) - mu * mu;
    float inv = rsqrtf(var + 1e-5f);

    char* ob = (char*)out;
    uint32_t rb = (uint32_t)(row & 127) * 128;
    int mb6 = (row >> 7) * 6;
    #pragma unroll
    for (int j = 0; j < 3; j++) {
        int k = (lane + 32 * j) * 4;
        float4 gv = *(const float4*)&g[k];
        float4 bv = *(const float4*)&b[k];
        float o0 = (v[j].x - mu) * inv * gv.x + bv.x;
        float o1 = (v[j].y - mu) * inv * gv.y + bv.y;
        float o2 = (v[j].z - mu) * inv * gv.z + bv.z;
        float o3 = (v[j].w - mu) * inv * gv.w + bv.w;
        uint2 u;
        u.x = h2u(__floats2half2_rn(o0, o1));
        u.y = h2u(__floats2half2_rn(o2, o3));
        *(uint2*)(ob + (size_t)(mb6 + (k >> 6)) * 16384 + sw128(rb + (uint32_t)(k & 63) * 2)) = u;
    }
}

// ---- FP16 warp-MMA GEMM: bulk-copy loads (tail-issued) + ldmatrix fragments ----
#define HG_HDR 1024
#define HG_BUF 16384
#define HG_STAGE (2 * HG_BUF)
#define HG_SMEM (HG_HDR + 3 * HG_STAGE)

template<int EPI>
__global__ void __launch_bounds__(256)
hgemm(const __half* __restrict__ A, const __half* __restrict__ W,
      const float* __restrict__ bias, const float* __restrict__ R,
      void* __restrict__ Cv, __half* qO, __half* kO, __half* vO, int N, int K) {
    extern __shared__ char smem[];
    uint32_t sb = (uint32_t)__cvta_generic_to_shared(smem);
    int tid  = threadIdx.x;
    int lane = tid & 31, warp = tid >> 5;
    int wm = warp >> 2, wn = warp & 3;
    int l4 = lane >> 2, qq = lane & 3;
    int n0 = blockIdx.x * 128, m0 = blockIdx.y * 128;
    int KB = K >> 6;
    int mbA = blockIdx.y, nbB = blockIdx.x;
    const char* Ab = (const char*)A;
    const char* Wb = (const char*)W;

    uint32_t aRow = (uint32_t)((lane & 7) + ((lane >> 3) & 1) * 8);
    uint32_t aSel = (uint32_t)((lane >> 4) * 16);
    uint32_t bRow = (uint32_t)(((lane >> 4) & 1) * 8 + (lane & 7));
    uint32_t bSel = (uint32_t)(((lane >> 3) & 1) * 16);
    uint32_t xm   = (uint32_t)((lane & 7) << 4);
    uint32_t aBase = (uint32_t)(wm * 64) + aRow;
    uint32_t bBase = (uint32_t)(wn * 32) + bRow;

    if (tid < 3)
        asm volatile("mbarrier.init.shared.b64 [%0], 1;" :: "r"(sb + tid * 8) : "memory");
    __syncthreads();

    auto load = [&](int c) {
        int st = c % 3;
        uint32_t mb = sb + st * 8;
        uint32_t d  = sb + HG_HDR + (uint32_t)st * HG_STAGE;
        asm volatile("mbarrier.arrive.expect_tx.shared.b64 _, [%0], %1;"
                     :: "r"(mb), "r"((uint32_t)HG_STAGE) : "memory");
        bulk_ld(d,          Ab + (size_t)(mbA * KB + c) * HG_BUF, HG_BUF, mb);
        bulk_ld(d + HG_BUF, Wb + (size_t)(nbB * KB + c) * HG_BUF, HG_BUF, mb);
    };
    if (tid == 0) { load(0); load(1); }

    float acc[4][4][4];
    #pragma unroll
    for (int mt = 0; mt < 4; mt++)
        #pragma unroll
        for (int nt = 0; nt < 4; nt++)
            #pragma unroll
            for (int e = 0; e < 4; e++) acc[mt][nt][e] = 0.f;

    for (int c = 0; c < KB; c++) {
        int st = c % 3;
        mwait(sb + st * 8, (uint32_t)((c / 3) & 1));
        uint32_t As = sb + HG_HDR + (uint32_t)st * HG_STAGE;
        uint32_t Bs = As + HG_BUF;

        #pragma unroll
        for (int kk = 0; kk < 4; kk++) {
            uint32_t af[4][4], bf[4][2];
            #pragma unroll
            for (int mt = 0; mt < 4; mt++)
                ldsm4(af[mt][0], af[mt][1], af[mt][2], af[mt][3],
                      As + (aBase + mt * 16) * 128 + ((32u * kk + aSel) ^ xm));
            #pragma unroll
            for (int pr = 0; pr < 2; pr++)
                ldsm4(bf[2*pr][0], bf[2*pr][1], bf[2*pr+1][0], bf[2*pr+1][1],
                      Bs + (bBase + pr * 16) * 128 + ((32u * kk + bSel) ^ xm));
            #pragma unroll
            for (int mt = 0; mt < 4; mt++)
                #pragma unroll
                for (int nt = 0; nt < 4; nt++)
                    asm volatile(
                        "mma.sync.aligned.m16n8k16.row.col.f32.f16.f16.f32 "
                        "{%0,%1,%2,%3}, {%4,%5,%6,%7}, {%8,%9}, {%0,%1,%2,%3};"
                        : "+f"(acc[mt][nt][0]), "+f"(acc[mt][nt][1]),
                          "+f"(acc[mt][nt][2]), "+f"(acc[mt][nt][3])
                        : "r"(af[mt][0]), "r"(af[mt][1]), "r"(af[mt][2]), "r"(af[mt][3]),
                          "r"(bf[nt][0]), "r"(bf[nt][1]));
        }
        __syncthreads();
        if (c + 2 < KB && tid == 0) load(c + 2);
    }

    #pragma unroll
    for (int mt = 0; mt < 4; mt++) {
        #pragma unroll
        for (int nt = 0; nt < 4; nt++) {
            int nb = n0 + wn * 32 + nt * 8 + qq * 2;
            int mA = m0 + wm * 64 + mt * 16 + l4;
            float v0 = acc[mt][nt][0], v1 = acc[mt][nt][1];
            float v2 = acc[mt][nt][2], v3 = acc[mt][nt][3];
            if (EPI == 0) {
                int mat = nb / 384, nn = nb - mat * 384;
                int head = nn >> 6, d = nn & 63;
                int b_ = mA >> 9, tA = mA & 511;
                if (mat == 0) {
                    const float qs = 0.125f * 1.4426950408889634f;   // fold log2e
                    v0 *= qs; v1 *= qs; v2 *= qs; v3 *= qs;
                }
                if (mat < 2) {
                    __half* base = mat ? kO : qO;
                    size_t off0 = ((size_t)(b_ * HEADS + head) * TT + tA) * 64 + d;
                    *(__half2*)&base[off0]          = __floats2half2_rn(v0, v1);
                    *(__half2*)&base[off0 + 8 * 64] = __floats2half2_rn(v2, v3);
                } else {
                    size_t off0 = ((size_t)(b_ * HEADS + head) * 64 + d) * TT + tA;
                    vO[off0]          = __float2half_rn(v0);
                    vO[off0 + TT]     = __float2half_rn(v1);
                    vO[off0 + 8]      = __float2half_rn(v2);
                    vO[off0 + TT + 8] = __float2half_rn(v3);
                }
            } else if (EPI == 1) {
                float* Cf = (float*)Cv;
                size_t o0 = (size_t)mA * N + nb;
                size_t o1 = (size_t)(mA + 8) * N + nb;
                Cf[o0]     = v0 + bias[nb]     + R[o0];
                Cf[o0 + 1] = v1 + bias[nb + 1] + R[o0 + 1];
                Cf[o1]     = v2 + bias[nb]     + R[o1];
                Cf[o1 + 1] = v3 + bias[nb + 1] + R[o1 + 1];
            } else {
                char* Ch = (char*)Cv;
                v0 += bias[nb];     v1 += bias[nb + 1];
                v2 += bias[nb];     v3 += bias[nb + 1];
                v0 = v0 > 0.f ? v0 : 0.f;  v1 = v1 > 0.f ? v1 : 0.f;
                v2 = v2 > 0.f ? v2 : 0.f;  v3 = v3 > 0.f ? v3 : 0.f;
                int blk = (mA >> 7) * (N >> 6) + (nb >> 6);
                uint32_t b0 = sw128((uint32_t)(mA & 127) * 128 + (uint32_t)(nb & 63) * 2);
                uint32_t b1 = sw128((uint32_t)((mA + 8) & 127) * 128 + (uint32_t)(nb & 63) * 2);
                *(__half2*)(Ch + (size_t)blk * 16384 + b0) = __floats2half2_rn(v0, v1);
                *(__half2*)(Ch + (size_t)blk * 16384 + b1) = __floats2half2_rn(v2, v3);
            }
        }
    }
}

// ---- fp16 flash attention: ldmatrix K/V, base-2 softmax, 128-key pairs ----
#define KVB 8192
#define ATTN_SMEM (8 * KVB)   // 65536

__global__ void __launch_bounds__(256)
attn3_kernel(const __half* __restrict__ q, const __half* __restrict__ k,
             const __half* __restrict__ v, __half* __restrict__ o) {
    extern __shared__ char sm2[];
    uint32_t sbase = (uint32_t)__cvta_generic_to_shared(sm2);
    int tid = threadIdx.x, lane = tid & 31, warp = tid >> 5;
    int l4 = lane >> 2, qq = lane & 3;
    int bh = blockIdx.y;
    int q0 = (int)(gridDim.x - 1 - blockIdx.x) * 128;   // heavy tiles first
    int mrow = warp * 16 + l4, qg0 = q0 + mrow, qg1 = qg0 + 8;
    int pairs = (q0 + 128) >> 7;
    int lr = tid >> 2, lc = tid & 3;
    uint32_t lxm = (uint32_t)((lr & 7) << 4);
    const __half* kh = k + (size_t)bh * TT * 64;
    const __half* vh = v + (size_t)bh * 64 * TT;

    uint32_t bRow = (uint32_t)(((lane >> 4) & 1) * 8 + (lane & 7));
    uint32_t bSel = (uint32_t)(((lane >> 3) & 1) * 16);
    uint32_t xm   = (uint32_t)((lane & 7) << 4);

    #pragma unroll
    for (int j = 0; j < 2; j++) {
        #pragma unroll
        for (int it = 0; it < 2; it++) {
            uint32_t c16 = (uint32_t)(lc + it * 4) * 16;
            uint32_t dof = (uint32_t)lr * 128 + (c16 ^ lxm);
            cp16(sbase + (uint32_t)j * KVB + dof,
                 kh + (size_t)(j * 64 + lr) * 64 + (c16 >> 1));
            cp16(sbase + (uint32_t)(4 + j) * KVB + dof,
                 vh + (size_t)lr * TT + j * 64 + (c16 >> 1));
        }
    }
    asm volatile("cp.async.commit_group;");

    const uint32_t* qw = (const uint32_t*)(q + (size_t)bh * TT * 64);
    uint32_t qf[4][4];
    #pragma unroll
    for (int kk = 0; kk < 4; kk++) {
        int kb = kk * 8;
        qf[kk][0] = qw[qg0 * 32 + kb + qq];
        qf[kk][1] = qw[qg1 * 32 + kb + qq];
        qf[kk][2] = qw[qg0 * 32 + kb + qq + 4];
        qf[kk][3] = qw[qg1 * 32 + kb + qq + 4];
    }

    float Oa[8][4];
    #pragma unroll
    for (int nt = 0; nt < 8; nt++)
        #pragma unroll
        for (int e = 0; e < 4; e++) Oa[nt][e] = 0.f;
    float m0 = -1e30f, m1 = -1e30f, l0 = 0.f, l1 = 0.f;

    for (int p2 = 0; p2 < pairs; p2++) {
        asm volatile("cp.async.wait_group 0;");
        __syncthreads();
        if (p2 + 1 < pairs) {
            int sbuf = 2 * ((p2 + 1) & 1);
            int tbase = 2 * (p2 + 1);
            #pragma unroll
            for (int j = 0; j < 2; j++) {
                #pragma unroll
                for (int it = 0; it < 2; it++) {
                    uint32_t c16 = (uint32_t)(lc + it * 4) * 16;
                    uint32_t dof = (uint32_t)lr * 128 + (c16 ^ lxm);
                    cp16(sbase + (uint32_t)(sbuf + j) * KVB + dof,
                         kh + (size_t)((tbase + j) * 64 + lr) * 64 + (c16 >> 1));
                    cp16(sbase + (uint32_t)(4 + sbuf + j) * KVB + dof,
                         vh + (size_t)lr * TT + (tbase + j) * 64 + (c16 >> 1));
                }
            }
            asm volatile("cp.async.commit_group;");
        }

        #pragma unroll
        for (int j = 0; j < 2; j++) {
            int slot = 2 * (p2 & 1) + j;
            uint32_t Ks = sbase + (uint32_t)slot * KVB;
            uint32_t Vs = sbase + (uint32_t)(4 + slot) * KVB;
            int k0 = (2 * p2 + j) << 6;

            float s[8][4];
            #pragma unroll
            for (int nt = 0; nt < 8; nt++)
                #pragma unroll
                for (int e = 0; e < 4; e++) s[nt][e] = 0.f;
            #pragma unroll
            for (int kk = 0; kk < 4; kk++) {
                uint32_t bf[8][2];
                #pragma unroll
                for (int pr = 0; pr < 4; pr++)
                    ldsm4(bf[2*pr][0], bf[2*pr][1], bf[2*pr+1][0], bf[2*pr+1][1],
                          Ks + (bRow + pr * 16) * 128 + ((32u * kk + bSel) ^ xm));
                #pragma unroll
                for (int nt = 0; nt < 8; nt++)
                    asm volatile(
                        "mma.sync.aligned.m16n8k16.row.col.f32.f16.f16.f32 "
                        "{%0,%1,%2,%3}, {%4,%5,%6,%7}, {%8,%9}, {%0,%1,%2,%3};"
                        : "+f"(s[nt][0]), "+f"(s[nt][1]), "+f"(s[nt][2]), "+f"(s[nt][3])
                        : "r"(qf[kk][0]), "r"(qf[kk][1]), "r"(qf[kk][2]), "r"(qf[kk][3]),
                          "r"(bf[nt][0]), "r"(bf[nt][1]));
            }
            if (k0 + 63 > qg0) {
                #pragma unroll
                for (int nt = 0; nt < 8; nt++) {
                    int kg = k0 + nt * 8 + 2 * qq;
                    if (kg     > qg0) s[nt][0] = -1e30f;
                    if (kg + 1 > qg0) s[nt][1] = -1e30f;
                    if (kg     > qg1) s[nt][2] = -1e30f;
                    if (kg + 1 > qg1) s[nt][3] = -1e30f;
                }
            }
            float r0 = -1e30f, r1 = -1e30f;
            #pragma unroll
            for (int nt = 0; nt < 8; nt++) {
                r0 = fmaxf(r0, fmaxf(s[nt][0], s[nt][1]));
                r1 = fmaxf(r1, fmaxf(s[nt][2], s[nt][3]));
            }
            r0 = fmaxf(r0, __shfl_xor_sync(0xffffffffu, r0, 1));
            r0 = fmaxf(r0, __shfl_xor_sync(0xffffffffu, r0, 2));
            r1 = fmaxf(r1, __shfl_xor_sync(0xffffffffu, r1, 1));
            r1 = fmaxf(r1, __shfl_xor_sync(0xffffffffu, r1, 2));
            float mn0 = fmaxf(m0, r0), mn1 = fmaxf(m1, r1);
            float sc0 = exp2f(m0 - mn0), sc1 = exp2f(m1 - mn1);
            float rs0 = 0.f, rs1 = 0.f;
            #pragma unroll
            for (int nt = 0; nt < 8; nt++) {
                s[nt][0] = exp2f(s[nt][0] - mn0);
                s[nt][1] = exp2f(s[nt][1] - mn0);
                s[nt][2] = exp2f(s[nt][2] - mn1);
                s[nt][3] = exp2f(s[nt][3] - mn1);
                rs0 += s[nt][0] + s[nt][1];
                rs1 += s[nt][2] + s[nt][3];
            }
            rs0 += __shfl_xor_sync(0xffffffffu, rs0, 1);
            rs0 += __shfl_xor_sync(0xffffffffu, rs0, 2);
            rs1 += __shfl_xor_sync(0xffffffffu, rs1, 1);
            rs1 += __shfl_xor_sync(0xffffffffu, rs1, 2);
            l0 = l0 * sc0 + rs0;  l1 = l1 * sc1 + rs1;
            m0 = mn0;  m1 = mn1;
            #pragma unroll
            for (int nt = 0; nt < 8; nt++) {
                Oa[nt][0] *= sc0; Oa[nt][1] *= sc0;
                Oa[nt][2] *= sc1; Oa[nt][3] *= sc1;
            }

            #pragma unroll
            for (int kk = 0; kk < 4; kk++) {
                uint32_t af[4];
                af[0] = h2u(__floats2half2_rn(s[2*kk][0],   s[2*kk][1]));
                af[1] = h2u(__floats2half2_rn(s[2*kk][2],   s[2*kk][3]));
                af[2] = h2u(__floats2half2_rn(s[2*kk+1][0], s[2*kk+1][1]));
                af[3] = h2u(__floats2half2_rn(s[2*kk+1][2], s[2*kk+1][3]));
                uint32_t bf[8][2];
                #pragma unroll
                for (int pr = 0; pr < 4; pr++)
                    ldsm4(bf[2*pr][0], bf[2*pr][1], bf[2*pr+1][0], bf[2*pr+1][1],
                          Vs + (bRow + pr * 16) * 128 + ((32u * kk + bSel) ^ xm));
                #pragma unroll
                for (int nt = 0; nt < 8; nt++)
                    asm volatile(
                        "mma.sync.aligned.m16n8k16.row.col.f32.f16.f16.f32 "
                        "{%0,%1,%2,%3}, {%4,%5,%6,%7}, {%8,%9}, {%0,%1,%2,%3};"
                        : "+f"(Oa[nt][0]), "+f"(Oa[nt][1]), "+f"(Oa[nt][2]), "+f"(Oa[nt][3])
                        : "r"(af[0]), "r"(af[1]), "r"(af[2]), "r"(af[3]),
                          "r"(bf[nt][0]), "r"(bf[nt][1]));
            }
        }
    }

    int b_ = bh / HEADS, h_ = bh % HEADS;
    float inv0 = 1.f / l0, inv1 = 1.f / l1;
    char* ob = (char*)o;
    int row0 = b_ * TT + qg0, row1 = b_ * TT + qg1;
    size_t blk0 = (size_t)((row0 >> 7) * 6 + h_) * 16384;
    size_t blk1 = (size_t)((row1 >> 7) * 6 + h_) * 16384;
    uint32_t rb0 = (uint32_t)(row0 & 127) * 128, rb1 = (uint32_t)(row1 & 127) * 128;
    #pragma unroll
    for (int nt = 0; nt < 8; nt++) {
        uint32_t co = (uint32_t)(nt * 8 + 2 * qq) * 2;
        *(__half2*)(ob + blk0 + sw128(rb0 + co)) = __floats2half2_rn(Oa[nt][0] * inv0, Oa[nt][1] * inv0);
        *(__half2*)(ob + blk1 + sw128(rb1 + co)) = __floats2half2_rn(Oa[nt][2] * inv1, Oa[nt][3] * inv1);
    }
}

// ---------------- launch ----------------
extern "C" void kernel_launch(void* const* d_in, const int* in_sizes, int n_in,
                              void* d_out, int out_size) {
    const float* x   = (const float*)d_in[0];
    const float* Wq  = (const float*)d_in[1];
    const float* Wk  = (const float*)d_in[2];
    const float* Wv  = (const float*)d_in[3];
    const float* Wp  = (const float*)d_in[4];
    const float* bp  = (const float*)d_in[5];
    const float* g1  = (const float*)d_in[6];
    const float* b1  = (const float*)d_in[7];
    const float* g2  = (const float*)d_in[8];
    const float* b2  = (const float*)d_in[9];
    const float* W1  = (const float*)d_in[10];
    const float* bf1 = (const float*)d_in[11];
    const float* W2  = (const float*)d_in[12];
    const float* bf2 = (const float*)d_in[13];
    float* out = (float*)d_out;

    __half *h, *q, *k, *v, *o, *h2, *ff, *wqkv, *wp, *w1t, *w2t;
    cudaGetSymbolAddress((void**)&h,    g_h);
    cudaGetSymbolAddress((void**)&q,    g_q);
    cudaGetSymbolAddress((void**)&k,    g_k);
    cudaGetSymbolAddress((void**)&v,    g_v);
    cudaGetSymbolAddress((void**)&o,    g_o);
    cudaGetSymbolAddress((void**)&h2,   g_h2);
    cudaGetSymbolAddress((void**)&ff,   g_ff);
    cudaGetSymbolAddress((void**)&wqkv, g_wqkv);
    cudaGetSymbolAddress((void**)&wp,   g_wp);
    cudaGetSymbolAddress((void**)&w1t,  g_w1t);
    cudaGetSymbolAddress((void**)&w2t,  g_w2t);

    static bool attr_done = false;
    if (!attr_done) {
        cudaFuncSetAttribute(attn3_kernel, cudaFuncAttributeMaxDynamicSharedMemorySize, (int)ATTN_SMEM);
        cudaFuncSetAttribute(hgemm<0>, cudaFuncAttributeMaxDynamicSharedMemorySize, (int)HG_SMEM);
        cudaFuncSetAttribute(hgemm<1>, cudaFuncAttributeMaxDynamicSharedMemorySize, (int)HG_SMEM);
        cudaFuncSetAttribute(hgemm<2>, cudaFuncAttributeMaxDynamicSharedMemorySize, (int)HG_SMEM);
        attr_done = true;
    }

    trans_all<<<1728, dim3(32, 8)>>>(Wq, Wk, Wv, Wp, W1, W2, wqkv, wp, w1t, w2t);
    ln_kernel<<<ROWS / 8, 256>>>(x, g1, b1, h);
    hgemm<0><<<dim3(9, ROWS/128), 256, HG_SMEM>>>(h, wqkv, nullptr, nullptr, nullptr, q, k, v, 1152, 384);
    attn3_kernel<<<dim3(TT/128, BB*HEADS), 256, ATTN_SMEM>>>(q, k, v, o);
    hgemm<1><<<dim3(3, ROWS/128), 256, HG_SMEM>>>(o, wp, bp, x, out, nullptr, nullptr, nullptr, 384, 384);
    ln_kernel<<<ROWS / 8, 256>>>(out, g2, b2, h2);
    hgemm<2><<<dim3(12, ROWS/128), 256, HG_SMEM>>>(h2, w1t, bf1, nullptr, ff, nullptr, nullptr, nullptr, 1536, 384);
    hgemm<1><<<dim3(3, ROWS/128), 256, HG_SMEM>>>(ff, w2t, bf2, out, out, nullptr, nullptr, nullptr, 384, 1536);
}